// round 2
// baseline (speedup 1.0000x reference)
#include <cuda_runtime.h>
#include <math.h>

#define LSEQ 384
#define DF 640

// Output packing: single(384*384) | pair(384*384*128) | dms(384) | shape(384)
#define OUT_SINGLE 0
#define OUT_PAIR   147456
#define OUT_DMS    19021824
#define OUT_SHAPE  19022208

__device__ float g_hi[LSEQ * 512];
__device__ float g_hj[LSEQ * 512];
__device__ float g_d[LSEQ];
__device__ float g_s[LSEQ];

__device__ __forceinline__ void warp_red2(float& a, float& b) {
#pragma unroll
    for (int o = 16; o; o >>= 1) {
        a += __shfl_down_sync(0xffffffffu, a, o);
        b += __shfl_down_sync(0xffffffffu, b, o);
    }
}

// block-wide mean/rstd over n elements (256 threads). red: smem[16], mv: smem[2]
__device__ __forceinline__ void block_stats(float psum, float psq, float n,
                                            volatile float* red, volatile float* mv) {
    warp_red2(psum, psq);
    int w = threadIdx.x >> 5, l = threadIdx.x & 31;
    if (l == 0) { red[w] = psum; red[8 + w] = psq; }
    __syncthreads();
    if (threadIdx.x == 0) {
        float s = 0.f, q = 0.f;
#pragma unroll
        for (int k = 0; k < 8; k++) { s += red[k]; q += red[8 + k]; }
        float m = s / n, v = q / n - m * m;
        mv[0] = m;
        mv[1] = rsqrtf(v + 1e-5f);
    }
    __syncthreads();
}

__device__ __forceinline__ float block_sum(float p, volatile float* red) {
    float z = 0.f;
    warp_red2(p, z);
    int w = threadIdx.x >> 5, l = threadIdx.x & 31;
    if (l == 0) red[w] = p;
    __syncthreads();
    if (threadIdx.x == 0) {
        float s = 0.f;
#pragma unroll
        for (int k = 0; k < 8; k++) s += red[k];
        red[0] = s;
    }
    __syncthreads();
    float s = red[0];
    __syncthreads();
    return s;
}

__global__ __launch_bounds__(256) void rows_kernel(
    const float* __restrict__ feat,
    const float* __restrict__ sp_w, const float* __restrict__ sp_b,
    const float* __restrict__ sp_g, const float* __restrict__ sp_be,
    const float* __restrict__ dms_w1, const float* __restrict__ dms_b1,
    const float* __restrict__ dms_w2, const float* __restrict__ dms_b2,
    const float* __restrict__ sh_w1, const float* __restrict__ sh_b1,
    const float* __restrict__ sh_w2, const float* __restrict__ sh_b2,
    const float* __restrict__ ts_w1, const float* __restrict__ ts_b1,
    const float* __restrict__ ts_g, const float* __restrict__ ts_be,
    const float* __restrict__ ts_w2, const float* __restrict__ ts_b2,
    const float* __restrict__ tp_w1,
    float* __restrict__ out)
{
    __shared__ float fS[DF];
    __shared__ float sS[320];
    __shared__ float tS[160];
    __shared__ float uS[512];
    __shared__ float red[16];
    __shared__ float mv[2];

    const int i = blockIdx.x, tid = threadIdx.x;

    for (int c = tid; c < DF; c += 256) fS[c] = feat[i * DF + c];
    __syncthreads();

    // shared = LN(relu(f @ sp_w + sp_b), sp_g, sp_be)   (320)
    float psum = 0.f, psq = 0.f;
    for (int c = tid; c < 320; c += 256) {
        float acc = sp_b[c];
#pragma unroll 8
        for (int k = 0; k < DF; k++) acc = fmaf(fS[k], sp_w[k * 320 + c], acc);
        acc = fmaxf(acc, 0.f);
        sS[c] = acc;
        psum += acc;
        psq += acc * acc;
    }
    block_stats(psum, psq, 320.f, red, mv);
    {
        float m = mv[0], r = mv[1];
        for (int c = tid; c < 320; c += 256)
            sS[c] = (sS[c] - m) * r * sp_g[c] + sp_be[c];
    }
    __syncthreads();

    // dms head
    if (tid < 160) {
        float acc = dms_b1[tid];
#pragma unroll 8
        for (int k = 0; k < 320; k++) acc = fmaf(sS[k], dms_w1[k * 160 + tid], acc);
        tS[tid] = fmaxf(acc, 0.f);
    }
    __syncthreads();
    {
        float pd = (tid < 160) ? tS[tid] * dms_w2[tid] : 0.f;
        float dsum = block_sum(pd, red);
        if (tid == 0) {
            float v = dsum + dms_b2[0];
            g_d[i] = v;
            out[OUT_DMS + i] = v;
        }
    }
    __syncthreads();

    // shape head
    if (tid < 160) {
        float acc = sh_b1[tid];
#pragma unroll 8
        for (int k = 0; k < 320; k++) acc = fmaf(sS[k], sh_w1[k * 160 + tid], acc);
        tS[tid] = fmaxf(acc, 0.f);
    }
    __syncthreads();
    {
        float ps = (tid < 160) ? tS[tid] * sh_w2[tid] : 0.f;
        float ssum = block_sum(ps, red);
        if (tid == 0) {
            float v = ssum + sh_b2[0];
            g_s[i] = v;
            out[OUT_SHAPE + i] = v;
        }
    }

    // single = LN(relu(f @ ts_w1 + b)) @ ts_w2 + b2
    psum = 0.f; psq = 0.f;
    for (int c = tid; c < 512; c += 256) {
        float acc = ts_b1[c];
#pragma unroll 8
        for (int k = 0; k < DF; k++) acc = fmaf(fS[k], ts_w1[k * 512 + c], acc);
        acc = fmaxf(acc, 0.f);
        uS[c] = acc;
        psum += acc;
        psq += acc * acc;
    }
    block_stats(psum, psq, 512.f, red, mv);
    {
        float m = mv[0], r = mv[1];
        for (int c = tid; c < 512; c += 256)
            uS[c] = (uS[c] - m) * r * ts_g[c] + ts_be[c];
    }
    __syncthreads();
    for (int c = tid; c < 384; c += 256) {
        float acc = ts_b2[c];
#pragma unroll 8
        for (int k = 0; k < 512; k++) acc = fmaf(uS[k], ts_w2[k * 384 + c], acc);
        out[OUT_SINGLE + i * 384 + c] = acc;
    }

    // hi = f @ Wa, hj = f @ Wb  (Wa = tp_w1[0:640], Wb = tp_w1[640:1280])
    for (int c = tid; c < 512; c += 256) {
        float a = 0.f, b = 0.f;
#pragma unroll 8
        for (int k = 0; k < DF; k++) {
            float f = fS[k];
            a = fmaf(f, tp_w1[k * 512 + c], a);
            b = fmaf(f, tp_w1[(DF + k) * 512 + c], b);
        }
        g_hi[i * 512 + c] = a;
        g_hj[i * 512 + c] = b;
    }
}

// ---------------------------------------------------------------------------
// Pair kernel: block = (i, 32 consecutive j). 256 threads.
// smem: lnhT[512][36] | wT[64*256] | h2S[32*256] | hiS[512] | wcS[4*512] | mv[64]
// ---------------------------------------------------------------------------
#define PAIR_SMEM_FLOATS (512 * 36 + 64 * 256 + 32 * 256 + 512 + 4 * 512 + 64)
#define PAIR_SMEM_BYTES  (PAIR_SMEM_FLOATS * 4)

__global__ __launch_bounds__(256) void pair_kernel(
    const float* __restrict__ tp_w1, const float* __restrict__ tp_b1,
    const float* __restrict__ tp_g, const float* __restrict__ tp_be,
    const float* __restrict__ tp_w2, const float* __restrict__ tp_b2,
    const float* __restrict__ tp_w3, const float* __restrict__ tp_b3,
    float* __restrict__ out)
{
    extern __shared__ float sm[];
    float* lnhT = sm;                 // [512][36] transposed, padded
    float* wT   = lnhT + 512 * 36;    // weight K-tile (64x256, reused as 64x128)
    float* h2S  = wT + 64 * 256;      // [32][256]
    float* hiS  = h2S + 32 * 256;     // [512]
    float* wcS  = hiS + 512;          // [4][512]
    float* mv   = wcS + 2048;         // [32][2]

    const int i = blockIdx.y;
    const int j0 = blockIdx.x * 32;
    const int tid = threadIdx.x;

    for (int c = tid; c < 512; c += 256) hiS[c] = g_hi[i * 512 + c] + tp_b1[c];
    for (int c = tid; c < 2048; c += 256) wcS[c] = tp_w1[1280 * 512 + c];
    __syncthreads();

    // --- Stage A: h = relu(hi + hj + chem@Wc + b1); row stats ---
    const int jj = tid >> 3, sub = tid & 7;
    const int j = j0 + jj;
    const float di = g_d[i], si = g_s[i];
    const float dj = g_d[j], sj = g_s[j];
    const float c0 = di - dj, c1 = di * dj, c2 = si - sj, c3 = si * sj;
    const float* hjrow = g_hj + (size_t)j * 512;

    float psum = 0.f, psq = 0.f;
#pragma unroll 8
    for (int cc = 0; cc < 64; cc++) {
        int c = sub + 8 * cc;   // conflict-free transposed store pattern
        float v = hiS[c] + __ldg(hjrow + c)
                + c0 * wcS[c] + c1 * wcS[512 + c]
                + c2 * wcS[1024 + c] + c3 * wcS[1536 + c];
        v = fmaxf(v, 0.f);
        lnhT[c * 36 + jj] = v;
        psum += v;
        psq += v * v;
    }
#pragma unroll
    for (int o = 4; o; o >>= 1) {
        psum += __shfl_down_sync(0xffffffffu, psum, o, 8);
        psq  += __shfl_down_sync(0xffffffffu, psq, o, 8);
    }
    if (sub == 0) {
        float m = psum / 512.f;
        float v = psq / 512.f - m * m;
        mv[jj * 2] = m;
        mv[jj * 2 + 1] = rsqrtf(v + 1e-5f);
    }
    __syncthreads();

    // normalize in-place: lnh = (h - m)*rstd*g + be
    for (int e = tid; e < 512 * 32; e += 256) {
        int c = e >> 5, jx = e & 31;
        float v = lnhT[c * 36 + jx];
        lnhT[c * 36 + jx] = (v - mv[jx * 2]) * mv[jx * 2 + 1] * __ldg(tp_g + c) + __ldg(tp_be + c);
    }

    // --- GEMM1: h2[32][256] = relu(lnh[32][512] @ W2[512][256] + b2) ---
    const int tx = tid & 31, ty = tid >> 5;
    float acc[4][8];
#pragma unroll
    for (int rr = 0; rr < 4; rr++)
#pragma unroll
        for (int u = 0; u < 8; u++) acc[rr][u] = 0.f;

    for (int kb = 0; kb < 8; kb++) {
        __syncthreads();
        const float4* src = (const float4*)(tp_w2 + kb * 64 * 256);
        float4* dst = (float4*)wT;
        for (int idx = tid; idx < 64 * 64; idx += 256) dst[idx] = src[idx];
        __syncthreads();
#pragma unroll 4
        for (int k = 0; k < 64; k++) {
            float4 a4 = *(const float4*)&lnhT[(kb * 64 + k) * 36 + ty * 4];
            float w[8];
#pragma unroll
            for (int u = 0; u < 8; u++) w[u] = wT[k * 256 + tx + 32 * u];
            float av[4] = {a4.x, a4.y, a4.z, a4.w};
#pragma unroll
            for (int rr = 0; rr < 4; rr++)
#pragma unroll
                for (int u = 0; u < 8; u++)
                    acc[rr][u] = fmaf(av[rr], w[u], acc[rr][u]);
        }
    }
    __syncthreads();
#pragma unroll
    for (int rr = 0; rr < 4; rr++)
#pragma unroll
        for (int u = 0; u < 8; u++) {
            int c = tx + 32 * u;
            h2S[(ty * 4 + rr) * 256 + c] = fmaxf(acc[rr][u] + __ldg(tp_b2 + c), 0.f);
        }

    // --- GEMM2: pair[32][128] = h2[32][256] @ W3[256][128] + b3 ---
    float acc2[4][4];
#pragma unroll
    for (int rr = 0; rr < 4; rr++)
#pragma unroll
        for (int u = 0; u < 4; u++) acc2[rr][u] = 0.f;

    for (int kb = 0; kb < 4; kb++) {
        __syncthreads();
        const float4* src = (const float4*)(tp_w3 + kb * 64 * 128);
        float4* dst = (float4*)wT;
        for (int idx = tid; idx < 64 * 32; idx += 256) dst[idx] = src[idx];
        __syncthreads();
#pragma unroll 4
        for (int k = 0; k < 64; k++) {
            float a[4];
#pragma unroll
            for (int rr = 0; rr < 4; rr++) a[rr] = h2S[(ty * 4 + rr) * 256 + kb * 64 + k];
            float w[4];
#pragma unroll
            for (int u = 0; u < 4; u++) w[u] = wT[k * 128 + tx + 32 * u];
#pragma unroll
            for (int rr = 0; rr < 4; rr++)
#pragma unroll
                for (int u = 0; u < 4; u++)
                    acc2[rr][u] = fmaf(a[rr], w[u], acc2[rr][u]);
        }
    }

#pragma unroll
    for (int rr = 0; rr < 4; rr++) {
        int jrow = j0 + ty * 4 + rr;
        size_t base = (size_t)OUT_PAIR + ((size_t)i * 384 + jrow) * 128;
#pragma unroll
        for (int u = 0; u < 4; u++) {
            int c = tx + 32 * u;
            out[base + c] = acc2[rr][u] + __ldg(tp_b3 + c);
        }
    }
}

extern "C" void kernel_launch(void* const* d_in, const int* in_sizes, int n_in,
                              void* d_out, int out_size) {
    const float* feat   = (const float*)d_in[0];
    const float* sp_w   = (const float*)d_in[1];
    const float* sp_b   = (const float*)d_in[2];
    const float* sp_g   = (const float*)d_in[3];
    const float* sp_be  = (const float*)d_in[4];
    const float* dms_w1 = (const float*)d_in[5];
    const float* dms_b1 = (const float*)d_in[6];
    const float* dms_w2 = (const float*)d_in[7];
    const float* dms_b2 = (const float*)d_in[8];
    const float* sh_w1  = (const float*)d_in[9];
    const float* sh_b1  = (const float*)d_in[10];
    const float* sh_w2  = (const float*)d_in[11];
    const float* sh_b2  = (const float*)d_in[12];
    const float* ts_w1  = (const float*)d_in[13];
    const float* ts_b1  = (const float*)d_in[14];
    const float* ts_g   = (const float*)d_in[15];
    const float* ts_be  = (const float*)d_in[16];
    const float* ts_w2  = (const float*)d_in[17];
    const float* ts_b2  = (const float*)d_in[18];
    const float* tp_w1  = (const float*)d_in[19];
    const float* tp_b1  = (const float*)d_in[20];
    const float* tp_g   = (const float*)d_in[21];
    const float* tp_be  = (const float*)d_in[22];
    const float* tp_w2  = (const float*)d_in[23];
    const float* tp_b2  = (const float*)d_in[24];
    const float* tp_w3  = (const float*)d_in[25];
    const float* tp_b3  = (const float*)d_in[26];
    float* out = (float*)d_out;

    cudaFuncSetAttribute(pair_kernel,
                         cudaFuncAttributeMaxDynamicSharedMemorySize,
                         PAIR_SMEM_BYTES);

    rows_kernel<<<LSEQ, 256>>>(feat,
                               sp_w, sp_b, sp_g, sp_be,
                               dms_w1, dms_b1, dms_w2, dms_b2,
                               sh_w1, sh_b1, sh_w2, sh_b2,
                               ts_w1, ts_b1, ts_g, ts_be,
                               ts_w2, ts_b2,
                               tp_w1,
                               out);

    pair_kernel<<<dim3(12, LSEQ), 256, PAIR_SMEM_BYTES>>>(
        tp_w1, tp_b1, tp_g, tp_be, tp_w2, tp_b2, tp_w3, tp_b3, out);
}

// round 3
// speedup vs baseline: 2.3582x; 2.3582x over previous
#include <cuda_runtime.h>
#include <math.h>
#include <stdint.h>

#define LSEQ 384
#define DF 640

// Output packing: single(384*384) | pair(384*384*128) | dms(384) | shape(384)
#define OUT_SINGLE 0
#define OUT_PAIR   147456
#define OUT_DMS    19021824
#define OUT_SHAPE  19022208

__device__ __align__(16) float g_hi[LSEQ * 512];
__device__ __align__(16) float g_hj[LSEQ * 512];
__device__ float g_d[LSEQ];
__device__ float g_s[LSEQ];
// tf32-pre-rounded weights for the pair GEMMs
__device__ __align__(16) float g_w2t[512 * 256];
__device__ __align__(16) float g_w3t[256 * 128];

// ---------------------------------------------------------------------------
// helpers
// ---------------------------------------------------------------------------
__device__ __forceinline__ uint32_t tf32r(float x) {
    uint32_t y;
    asm("cvt.rna.tf32.f32 %0, %1;" : "=r"(y) : "f"(x));
    return y;
}

__device__ __forceinline__ void mma_tf32(float* d, uint32_t a0, uint32_t a1,
                                         uint32_t a2, uint32_t a3,
                                         uint32_t b0, uint32_t b1) {
    asm volatile(
        "mma.sync.aligned.m16n8k8.row.col.f32.tf32.tf32.f32 "
        "{%0,%1,%2,%3}, {%4,%5,%6,%7}, {%8,%9}, {%0,%1,%2,%3};"
        : "+f"(d[0]), "+f"(d[1]), "+f"(d[2]), "+f"(d[3])
        : "r"(a0), "r"(a1), "r"(a2), "r"(a3), "r"(b0), "r"(b1));
}

__device__ __forceinline__ void cpasync16(void* dst, const void* src) {
    uint32_t d = (uint32_t)__cvta_generic_to_shared(dst);
    asm volatile("cp.async.ca.shared.global [%0], [%1], 16;" :: "r"(d), "l"(src));
}
__device__ __forceinline__ void cpcommit() {
    asm volatile("cp.async.commit_group;");
}
template <int N>
__device__ __forceinline__ void cpwait() {
    asm volatile("cp.async.wait_group %0;" :: "n"(N));
}

__device__ __forceinline__ void warp_red2(float& a, float& b) {
#pragma unroll
    for (int o = 16; o; o >>= 1) {
        a += __shfl_down_sync(0xffffffffu, a, o);
        b += __shfl_down_sync(0xffffffffu, b, o);
    }
}

__device__ __forceinline__ void block_stats(float psum, float psq, float n,
                                            volatile float* red, volatile float* mv) {
    warp_red2(psum, psq);
    int w = threadIdx.x >> 5, l = threadIdx.x & 31;
    if (l == 0) { red[w] = psum; red[8 + w] = psq; }
    __syncthreads();
    if (threadIdx.x == 0) {
        float s = 0.f, q = 0.f;
#pragma unroll
        for (int k = 0; k < 8; k++) { s += red[k]; q += red[8 + k]; }
        float m = s / n, v = q / n - m * m;
        mv[0] = m;
        mv[1] = rsqrtf(v + 1e-5f);
    }
    __syncthreads();
}

__device__ __forceinline__ float block_sum(float p, volatile float* red) {
    float z = 0.f;
    warp_red2(p, z);
    int w = threadIdx.x >> 5, l = threadIdx.x & 31;
    if (l == 0) red[w] = p;
    __syncthreads();
    if (threadIdx.x == 0) {
        float s = 0.f;
#pragma unroll
        for (int k = 0; k < 8; k++) s += red[k];
        red[0] = s;
    }
    __syncthreads();
    float s = red[0];
    __syncthreads();
    return s;
}

// ---------------------------------------------------------------------------
// prep: round pair-GEMM weights to tf32 once
// ---------------------------------------------------------------------------
__global__ void prep_kernel(const float* __restrict__ w2, const float* __restrict__ w3) {
    const int N2 = 512 * 256, N3 = 256 * 128;
    for (int t = blockIdx.x * blockDim.x + threadIdx.x; t < N2 + N3;
         t += gridDim.x * blockDim.x) {
        if (t < N2) g_w2t[t] = __uint_as_float(tf32r(w2[t]));
        else        g_w3t[t - N2] = __uint_as_float(tf32r(w3[t - N2]));
    }
}

// ---------------------------------------------------------------------------
// rows kernel (unchanged from passing round)
// ---------------------------------------------------------------------------
__global__ __launch_bounds__(256) void rows_kernel(
    const float* __restrict__ feat,
    const float* __restrict__ sp_w, const float* __restrict__ sp_b,
    const float* __restrict__ sp_g, const float* __restrict__ sp_be,
    const float* __restrict__ dms_w1, const float* __restrict__ dms_b1,
    const float* __restrict__ dms_w2, const float* __restrict__ dms_b2,
    const float* __restrict__ sh_w1, const float* __restrict__ sh_b1,
    const float* __restrict__ sh_w2, const float* __restrict__ sh_b2,
    const float* __restrict__ ts_w1, const float* __restrict__ ts_b1,
    const float* __restrict__ ts_g, const float* __restrict__ ts_be,
    const float* __restrict__ ts_w2, const float* __restrict__ ts_b2,
    const float* __restrict__ tp_w1,
    float* __restrict__ out)
{
    __shared__ float fS[DF];
    __shared__ float sS[320];
    __shared__ float tS[160];
    __shared__ float uS[512];
    __shared__ float red[16];
    __shared__ float mv[2];

    const int i = blockIdx.x, tid = threadIdx.x;

    for (int c = tid; c < DF; c += 256) fS[c] = feat[i * DF + c];
    __syncthreads();

    float psum = 0.f, psq = 0.f;
    for (int c = tid; c < 320; c += 256) {
        float acc = sp_b[c];
#pragma unroll 8
        for (int k = 0; k < DF; k++) acc = fmaf(fS[k], sp_w[k * 320 + c], acc);
        acc = fmaxf(acc, 0.f);
        sS[c] = acc;
        psum += acc;
        psq += acc * acc;
    }
    block_stats(psum, psq, 320.f, red, mv);
    {
        float m = mv[0], r = mv[1];
        for (int c = tid; c < 320; c += 256)
            sS[c] = (sS[c] - m) * r * sp_g[c] + sp_be[c];
    }
    __syncthreads();

    if (tid < 160) {
        float acc = dms_b1[tid];
#pragma unroll 8
        for (int k = 0; k < 320; k++) acc = fmaf(sS[k], dms_w1[k * 160 + tid], acc);
        tS[tid] = fmaxf(acc, 0.f);
    }
    __syncthreads();
    {
        float pd = (tid < 160) ? tS[tid] * dms_w2[tid] : 0.f;
        float dsum = block_sum(pd, red);
        if (tid == 0) {
            float v = dsum + dms_b2[0];
            g_d[i] = v;
            out[OUT_DMS + i] = v;
        }
    }
    __syncthreads();

    if (tid < 160) {
        float acc = sh_b1[tid];
#pragma unroll 8
        for (int k = 0; k < 320; k++) acc = fmaf(sS[k], sh_w1[k * 160 + tid], acc);
        tS[tid] = fmaxf(acc, 0.f);
    }
    __syncthreads();
    {
        float ps = (tid < 160) ? tS[tid] * sh_w2[tid] : 0.f;
        float ssum = block_sum(ps, red);
        if (tid == 0) {
            float v = ssum + sh_b2[0];
            g_s[i] = v;
            out[OUT_SHAPE + i] = v;
        }
    }

    psum = 0.f; psq = 0.f;
    for (int c = tid; c < 512; c += 256) {
        float acc = ts_b1[c];
#pragma unroll 8
        for (int k = 0; k < DF; k++) acc = fmaf(fS[k], ts_w1[k * 512 + c], acc);
        acc = fmaxf(acc, 0.f);
        uS[c] = acc;
        psum += acc;
        psq += acc * acc;
    }
    block_stats(psum, psq, 512.f, red, mv);
    {
        float m = mv[0], r = mv[1];
        for (int c = tid; c < 512; c += 256)
            uS[c] = (uS[c] - m) * r * ts_g[c] + ts_be[c];
    }
    __syncthreads();
    for (int c = tid; c < 384; c += 256) {
        float acc = ts_b2[c];
#pragma unroll 8
        for (int k = 0; k < 512; k++) acc = fmaf(uS[k], ts_w2[k * 384 + c], acc);
        out[OUT_SINGLE + i * 384 + c] = acc;
    }

    for (int c = tid; c < 512; c += 256) {
        float a = 0.f, b = 0.f;
#pragma unroll 8
        for (int k = 0; k < DF; k++) {
            float f = fS[k];
            a = fmaf(f, tp_w1[k * 512 + c], a);
            b = fmaf(f, tp_w1[(DF + k) * 512 + c], b);
        }
        g_hi[i * 512 + c] = a;
        g_hj[i * 512 + c] = b;
    }
}

// ---------------------------------------------------------------------------
// pair kernel: tf32 tensor cores. block = (jt, i), M=64 j rows.
// ---------------------------------------------------------------------------
#define PADH  524   // hA row stride (A operand GEMM1)
#define PADW1 264   // W2 tile row stride
#define PADH2 268   // h2 row stride (A operand GEMM2)
#define PADW2 136   // W3 tile row stride

#define OFF_H  0                     // 64*524 = 33536 (reused for h2: 64*268)
#define OFF_W  33536                 // 2*32*264 = 16896 (reused for W3: 2*32*136)
#define OFF_HI 50432                 // 512
#define OFF_WC 50944                 // 2048
#define OFF_MV 52992                 // 128
#define OFF_G  53120                 // 512
#define OFF_BE 53632                 // 512
#define OFF_B2 54144                 // 256
#define OFF_B3 54400                 // 128
#define PAIR_SMEM_FLOATS 54528
#define PAIR_SMEM_BYTES  (PAIR_SMEM_FLOATS * 4)

#define W2BUF (32 * PADW1)   // 8448
#define W3BUF (32 * PADW2)   // 4352

__global__ __launch_bounds__(256, 1) void pair_kernel(
    const float* __restrict__ tp_w1, const float* __restrict__ tp_b1,
    const float* __restrict__ tp_g, const float* __restrict__ tp_be,
    const float* __restrict__ tp_b2, const float* __restrict__ tp_b3,
    float* __restrict__ out)
{
    extern __shared__ float sm[];
    float* hA  = sm + OFF_H;
    float* wS  = sm + OFF_W;
    float* hiS = sm + OFF_HI;
    float* wcS = sm + OFF_WC;
    float* mvS = sm + OFF_MV;
    float* gS  = sm + OFF_G;
    float* beS = sm + OFF_BE;
    float* b2S = sm + OFF_B2;
    float* b3S = sm + OFF_B3;

    const int i = blockIdx.y;
    const int j0 = blockIdx.x * 64;
    const int tid = threadIdx.x;
    const int lane = tid & 31, warp = tid >> 5;
    const int wm = warp & 1;          // M group (0..1)
    const int wn = warp >> 1;         // N group (0..3)

    // ---- prefetch W2 tile 0 (overlaps stage A) ----
    for (int t = tid; t < 2048; t += 256) {
        int r = t >> 6, c4 = t & 63;
        cpasync16(wS + r * PADW1 + c4 * 4, g_w2t + r * 256 + c4 * 4);
    }
    cpcommit();

    // ---- misc loads ----
    for (int c = tid; c < 512; c += 256) {
        hiS[c] = g_hi[i * 512 + c] + tp_b1[c];
        gS[c]  = tp_g[c];
        beS[c] = tp_be[c];
    }
    for (int c = tid; c < 2048; c += 256) wcS[c] = tp_w1[1280 * 512 + c];
    if (tid < 256) b2S[tid] = tp_b2[tid];
    if (tid < 128) b3S[tid] = tp_b3[tid];
    __syncthreads();

    // ---- stage A: h = relu(hi + hj + chem@Wc + b1), row stats ----
    const int jj = tid >> 2, sub = tid & 3;
    const int j = j0 + jj;
    const float di = g_d[i], si = g_s[i];
    const float dj = g_d[j], sj = g_s[j];
    const float c0 = di - dj, c1 = di * dj, c2 = si - sj, c3 = si * sj;
    const float4* hj4 = (const float4*)(g_hj + (size_t)j * 512);
    float* hrow = hA + jj * PADH;

    float psum = 0.f, psq = 0.f;
#pragma unroll 4
    for (int cc = 0; cc < 32; cc++) {
        int q = sub + 4 * cc;       // float4 index
        float4 v4 = hj4[q];
        int c = q * 4;
        float4 o;
        o.x = fmaxf(hiS[c]     + v4.x + c0 * wcS[c]     + c1 * wcS[512 + c]     + c2 * wcS[1024 + c]     + c3 * wcS[1536 + c],     0.f);
        o.y = fmaxf(hiS[c + 1] + v4.y + c0 * wcS[c + 1] + c1 * wcS[512 + c + 1] + c2 * wcS[1024 + c + 1] + c3 * wcS[1536 + c + 1], 0.f);
        o.z = fmaxf(hiS[c + 2] + v4.z + c0 * wcS[c + 2] + c1 * wcS[512 + c + 2] + c2 * wcS[1024 + c + 2] + c3 * wcS[1536 + c + 2], 0.f);
        o.w = fmaxf(hiS[c + 3] + v4.w + c0 * wcS[c + 3] + c1 * wcS[512 + c + 3] + c2 * wcS[1024 + c + 3] + c3 * wcS[1536 + c + 3], 0.f);
        psum += o.x + o.y + o.z + o.w;
        psq  += o.x * o.x + o.y * o.y + o.z * o.z + o.w * o.w;
        *(float4*)(hrow + c) = o;
    }
    psum += __shfl_down_sync(0xffffffffu, psum, 2, 4);
    psq  += __shfl_down_sync(0xffffffffu, psq, 2, 4);
    psum += __shfl_down_sync(0xffffffffu, psum, 1, 4);
    psq  += __shfl_down_sync(0xffffffffu, psq, 1, 4);
    if (sub == 0) {
        float m = psum / 512.f;
        float v = psq / 512.f - m * m;
        mvS[2 * jj] = m;
        mvS[2 * jj + 1] = rsqrtf(v + 1e-5f);
    }
    __syncthreads();

    // LN + tf32 round
    {
        float m = mvS[2 * jj], r = mvS[2 * jj + 1];
#pragma unroll 4
        for (int cc = 0; cc < 32; cc++) {
            int c = (sub + 4 * cc) * 4;
            float4 v = *(float4*)(hrow + c);
            v.x = __uint_as_float(tf32r((v.x - m) * r * gS[c]     + beS[c]));
            v.y = __uint_as_float(tf32r((v.y - m) * r * gS[c + 1] + beS[c + 1]));
            v.z = __uint_as_float(tf32r((v.z - m) * r * gS[c + 2] + beS[c + 2]));
            v.w = __uint_as_float(tf32r((v.w - m) * r * gS[c + 3] + beS[c + 3]));
            *(float4*)(hrow + c) = v;
        }
    }
    __syncthreads();

    // ---- GEMM1: h2[64][256] = relu(lnh[64][512] @ W2 + b2) ----
    float acc[2][8][4];
#pragma unroll
    for (int mt = 0; mt < 2; mt++)
#pragma unroll
        for (int nf = 0; nf < 8; nf++)
#pragma unroll
            for (int e = 0; e < 4; e++) acc[mt][nf][e] = 0.f;

    const int ar = wm * 32 + (lane >> 2);
    const int ak = lane & 3;
    const int bk = lane & 3;
    const int bn = lane >> 2;

    for (int kb = 0; kb < 16; kb++) {
        if (kb < 15) {
            float* dstB = wS + ((kb + 1) & 1) * W2BUF;
            const float* srcB = g_w2t + (kb + 1) * 32 * 256;
            for (int t = tid; t < 2048; t += 256) {
                int r = t >> 6, c4 = t & 63;
                cpasync16(dstB + r * PADW1 + c4 * 4, srcB + r * 256 + c4 * 4);
            }
            cpcommit();
            cpwait<1>();
        } else {
            cpwait<0>();
        }
        __syncthreads();
        const float* wt = wS + (kb & 1) * W2BUF;
#pragma unroll
        for (int k8 = 0; k8 < 4; k8++) {
            int kg = kb * 32 + k8 * 8;
            uint32_t a[2][4];
#pragma unroll
            for (int mt = 0; mt < 2; mt++) {
                int r = ar + mt * 16;
                a[mt][0] = __float_as_uint(hA[r * PADH + kg + ak]);
                a[mt][1] = __float_as_uint(hA[(r + 8) * PADH + kg + ak]);
                a[mt][2] = __float_as_uint(hA[r * PADH + kg + ak + 4]);
                a[mt][3] = __float_as_uint(hA[(r + 8) * PADH + kg + ak + 4]);
            }
#pragma unroll
            for (int nf = 0; nf < 8; nf++) {
                int nc = wn * 64 + nf * 8 + bn;
                uint32_t b0 = __float_as_uint(wt[(k8 * 8 + bk) * PADW1 + nc]);
                uint32_t b1 = __float_as_uint(wt[(k8 * 8 + bk + 4) * PADW1 + nc]);
                mma_tf32(acc[0][nf], a[0][0], a[0][1], a[0][2], a[0][3], b0, b1);
                mma_tf32(acc[1][nf], a[1][0], a[1][1], a[1][2], a[1][3], b0, b1);
            }
        }
        __syncthreads();
    }

    // prefetch W3 tile 0 (w region free now)
    for (int t = tid; t < 1024; t += 256) {
        int r = t >> 5, c4 = t & 31;
        cpasync16(wS + r * PADW2 + c4 * 4, g_w3t + r * 128 + c4 * 4);
    }
    cpcommit();

    // epilogue1: bias + relu + tf32 round -> h2 (overwrites hA region)
    float* h2 = hA;
#pragma unroll
    for (int mt = 0; mt < 2; mt++) {
        int r = ar + mt * 16;
#pragma unroll
        for (int nf = 0; nf < 8; nf++) {
            int cb = wn * 64 + nf * 8 + 2 * (lane & 3);
            float2 v0, v1;
            v0.x = __uint_as_float(tf32r(fmaxf(acc[mt][nf][0] + b2S[cb], 0.f)));
            v0.y = __uint_as_float(tf32r(fmaxf(acc[mt][nf][1] + b2S[cb + 1], 0.f)));
            v1.x = __uint_as_float(tf32r(fmaxf(acc[mt][nf][2] + b2S[cb], 0.f)));
            v1.y = __uint_as_float(tf32r(fmaxf(acc[mt][nf][3] + b2S[cb + 1], 0.f)));
            *(float2*)(h2 + r * PADH2 + cb) = v0;
            *(float2*)(h2 + (r + 8) * PADH2 + cb) = v1;
        }
    }
    __syncthreads();

    // ---- GEMM2: pair[64][128] = h2[64][256] @ W3 + b3 ----
    float acc2[2][4][4];
#pragma unroll
    for (int mt = 0; mt < 2; mt++)
#pragma unroll
        for (int nf = 0; nf < 4; nf++)
#pragma unroll
            for (int e = 0; e < 4; e++) acc2[mt][nf][e] = 0.f;

    for (int kb = 0; kb < 8; kb++) {
        if (kb < 7) {
            float* dstB = wS + ((kb + 1) & 1) * W3BUF;
            const float* srcB = g_w3t + (kb + 1) * 32 * 128;
            for (int t = tid; t < 1024; t += 256) {
                int r = t >> 5, c4 = t & 31;
                cpasync16(dstB + r * PADW2 + c4 * 4, srcB + r * 128 + c4 * 4);
            }
            cpcommit();
            cpwait<1>();
        } else {
            cpwait<0>();
        }
        __syncthreads();
        const float* wt = wS + (kb & 1) * W3BUF;
#pragma unroll
        for (int k8 = 0; k8 < 4; k8++) {
            int kg = kb * 32 + k8 * 8;
            uint32_t a[2][4];
#pragma unroll
            for (int mt = 0; mt < 2; mt++) {
                int r = ar + mt * 16;
                a[mt][0] = __float_as_uint(h2[r * PADH2 + kg + ak]);
                a[mt][1] = __float_as_uint(h2[(r + 8) * PADH2 + kg + ak]);
                a[mt][2] = __float_as_uint(h2[r * PADH2 + kg + ak + 4]);
                a[mt][3] = __float_as_uint(h2[(r + 8) * PADH2 + kg + ak + 4]);
            }
#pragma unroll
            for (int nf = 0; nf < 4; nf++) {
                int nc = wn * 32 + nf * 8 + bn;
                uint32_t b0 = __float_as_uint(wt[(k8 * 8 + bk) * PADW2 + nc]);
                uint32_t b1 = __float_as_uint(wt[(k8 * 8 + bk + 4) * PADW2 + nc]);
                mma_tf32(acc2[0][nf], a[0][0], a[0][1], a[0][2], a[0][3], b0, b1);
                mma_tf32(acc2[1][nf], a[1][0], a[1][1], a[1][2], a[1][3], b0, b1);
            }
        }
        __syncthreads();
    }

    // epilogue2: bias + store
#pragma unroll
    for (int mt = 0; mt < 2; mt++) {
        int r = ar + mt * 16;
#pragma unroll
        for (int nf = 0; nf < 4; nf++) {
            int cb = wn * 32 + nf * 8 + 2 * (lane & 3);
            float2 v0, v1;
            v0.x = acc2[mt][nf][0] + b3S[cb];
            v0.y = acc2[mt][nf][1] + b3S[cb + 1];
            v1.x = acc2[mt][nf][2] + b3S[cb];
            v1.y = acc2[mt][nf][3] + b3S[cb + 1];
            size_t base0 = (size_t)OUT_PAIR + ((size_t)i * 384 + j0 + r) * 128 + cb;
            size_t base1 = (size_t)OUT_PAIR + ((size_t)i * 384 + j0 + r + 8) * 128 + cb;
            *(float2*)(out + base0) = v0;
            *(float2*)(out + base1) = v1;
        }
    }
}

extern "C" void kernel_launch(void* const* d_in, const int* in_sizes, int n_in,
                              void* d_out, int out_size) {
    const float* feat   = (const float*)d_in[0];
    const float* sp_w   = (const float*)d_in[1];
    const float* sp_b   = (const float*)d_in[2];
    const float* sp_g   = (const float*)d_in[3];
    const float* sp_be  = (const float*)d_in[4];
    const float* dms_w1 = (const float*)d_in[5];
    const float* dms_b1 = (const float*)d_in[6];
    const float* dms_w2 = (const float*)d_in[7];
    const float* dms_b2 = (const float*)d_in[8];
    const float* sh_w1  = (const float*)d_in[9];
    const float* sh_b1  = (const float*)d_in[10];
    const float* sh_w2  = (const float*)d_in[11];
    const float* sh_b2  = (const float*)d_in[12];
    const float* ts_w1  = (const float*)d_in[13];
    const float* ts_b1  = (const float*)d_in[14];
    const float* ts_g   = (const float*)d_in[15];
    const float* ts_be  = (const float*)d_in[16];
    const float* ts_w2  = (const float*)d_in[17];
    const float* ts_b2  = (const float*)d_in[18];
    const float* tp_w1  = (const float*)d_in[19];
    const float* tp_b1  = (const float*)d_in[20];
    const float* tp_g   = (const float*)d_in[21];
    const float* tp_be  = (const float*)d_in[22];
    const float* tp_w2  = (const float*)d_in[23];
    const float* tp_b2  = (const float*)d_in[24];
    const float* tp_w3  = (const float*)d_in[25];
    const float* tp_b3  = (const float*)d_in[26];
    float* out = (float*)d_out;

    cudaFuncSetAttribute(pair_kernel,
                         cudaFuncAttributeMaxDynamicSharedMemorySize,
                         PAIR_SMEM_BYTES);

    prep_kernel<<<160, 256>>>(tp_w2, tp_w3);

    rows_kernel<<<LSEQ, 256>>>(feat,
                               sp_w, sp_b, sp_g, sp_be,
                               dms_w1, dms_b1, dms_w2, dms_b2,
                               sh_w1, sh_b1, sh_w2, sh_b2,
                               ts_w1, ts_b1, ts_g, ts_be,
                               ts_w2, ts_b2,
                               tp_w1,
                               out);

    pair_kernel<<<dim3(6, LSEQ), 256, PAIR_SMEM_BYTES>>>(
        tp_w1, tp_b1, tp_g, tp_be, tp_b2, tp_b3, out);
}